// round 12
// baseline (speedup 1.0000x reference)
#include <cuda_runtime.h>
#include <cuda_fp16.h>
#include <math.h>
#include <stdint.h>

#define BB   2
#define SS   2048
#define DD   1024
#define HH   16
#define DKK  64
#define MM   (BB*SS)          // 4096

// ---------------- scratch (no cudaMalloc allowed) ----------------
__device__ __half g_inh[3u*MM*DD];  // fp16 inputs (query,key,value)
__device__ __half g_wh [4u*DD*DD];  // fp16 weights (wq,wk,wv,wo)
__device__ __half g_mh [BB*SS];     // fp16 mask (0/1)
__device__ __half g_q  [MM*DD];     // Q projection  [token][1024]
__device__ __half g_k  [MM*DD];     // K projection  [token][1024]
__device__ __half g_vt [MM*DD];     // V projection TRANSPOSED [1024 d][4096 token]
__device__ __half g_x  [MM*DD];     // attention out [token][1024]

// ---------------- helpers ----------------
__device__ __forceinline__ unsigned smem_u32(const void* p) {
    return (unsigned)__cvta_generic_to_shared(p);
}
__device__ __forceinline__ void cp16s(unsigned sa, const void* g) {
    asm volatile("cp.async.cg.shared.global [%0], [%1], 16;" :: "r"(sa), "l"(g));
}
__device__ __forceinline__ void mma16(float d[4],
                                      unsigned a0, unsigned a1, unsigned a2, unsigned a3,
                                      unsigned b0, unsigned b1) {
    asm volatile(
        "mma.sync.aligned.m16n8k16.row.col.f32.f16.f16.f32 "
        "{%0,%1,%2,%3}, {%4,%5,%6,%7}, {%8,%9}, {%0,%1,%2,%3};"
        : "+f"(d[0]), "+f"(d[1]), "+f"(d[2]), "+f"(d[3])
        : "r"(a0), "r"(a1), "r"(a2), "r"(a3), "r"(b0), "r"(b1));
}
__device__ __forceinline__ void ldsm4(unsigned& r0, unsigned& r1, unsigned& r2, unsigned& r3,
                                      unsigned a) {
    asm volatile("ldmatrix.sync.aligned.m8n8.x4.shared.b16 {%0,%1,%2,%3}, [%4];"
                 : "=r"(r0), "=r"(r1), "=r"(r2), "=r"(r3) : "r"(a));
}
__device__ __forceinline__ unsigned pack_h2(float a, float b) {
    __half2 h = __floats2half2_rn(a, b);
    return *reinterpret_cast<unsigned*>(&h);
}
__device__ __forceinline__ unsigned ex2h2(unsigned x) {
    unsigned r;
    asm("ex2.approx.f16x2 %0, %1;" : "=r"(r) : "r"(x));
    return r;
}

// ---------------- fp32 -> fp16 conversion pass (+ mask to half) ----------------
__global__ void tohalf(const float* __restrict__ q, const float* __restrict__ k,
                       const float* __restrict__ v,
                       const float* __restrict__ wq, const float* __restrict__ wk,
                       const float* __restrict__ wv, const float* __restrict__ wo,
                       const int* __restrict__ mask,
                       __half* __restrict__ dinh, __half* __restrict__ dwh,
                       __half* __restrict__ dmh)
{
    const int z = blockIdx.z;
    int i = (blockIdx.x * blockDim.x + threadIdx.x) * 4;
    if (z == 7) {
        if (i < BB * SS) {
            int4 m = *(const int4*)(mask + i);
            __half h[4];
            h[0] = __int2half_rn(m.x); h[1] = __int2half_rn(m.y);
            h[2] = __int2half_rn(m.z); h[3] = __int2half_rn(m.w);
            *(uint2*)(dmh + i) = *(uint2*)h;
        }
        return;
    }
    const float* src; __half* dst; int n;
    if (z < 3) {
        src = (z == 0) ? q : (z == 1) ? k : v;
        dst = dinh + (size_t)z * MM * DD;  n = MM * DD;
    } else {
        src = (z == 3) ? wq : (z == 4) ? wk : (z == 5) ? wv : wo;
        dst = dwh + (size_t)(z - 3) * DD * DD;  n = DD * DD;
    }
    if (i < n) {
        float4 t = *(const float4*)(src + i);
        uint2 u;
        u.x = pack_h2(t.x, t.y);
        u.y = pack_h2(t.z, t.w);
        *(uint2*)(dst + i) = u;
    }
}

// ---------------- GEMM (fp16 mma + ldmatrix, 3-stage cp.async, 1 sync/chunk) --------
#define GBKH 64
#define GSTRW 36
#define STGW2 (128 * GSTRW)
#define GEMM_SMEM (3 * 2 * STGW2 * 4)

__global__ __launch_bounds__(256, 2) void gemm_h(
    const __half* __restrict__ A0, const __half* __restrict__ A1,
    const __half* __restrict__ W0, const __half* __restrict__ W1,
    const float* __restrict__ b0p, const float* __restrict__ b1p,
    void* __restrict__ C0v, void* __restrict__ C1v,
    int N, int out_fp32, int bias_rows)
{
    const int z = blockIdx.z;
    const __half* __restrict__ A    = z ? A1 : A0;
    const __half* __restrict__ W    = z ? W1 : W0;
    const float*  __restrict__ bias = z ? b1p : b0p;
    void* Cv = z ? C1v : C0v;
    const int K = DD;

    extern __shared__ __align__(16) unsigned gsm[];

    const int tid  = threadIdx.x;
    const int lane = tid & 31;
    const int wid  = tid >> 5;
    const int wm   = (wid & 3) * 32;
    const int wn   = (wid >> 2) * 64;
    const int m0   = blockIdx.y * 128;
    const int n0   = blockIdx.x * 128;
    const int lq   = lane >> 2;
    const int lr   = lane & 3;

    const int lrow0 = tid >> 3;
    const int loffh = (tid & 7) * 8;

    const unsigned lmB = (((lane & 7) + ((lane >> 4) << 3)) * GSTRW + ((lane >> 3) & 1) * 4) * 4;
    const unsigned lmA = (((lane & 7) + (((lane >> 3) & 1) << 3)) * GSTRW + (lane >> 4) * 4) * 4;

    float acc[2][8][4];
    #pragma unroll
    for (int mt = 0; mt < 2; ++mt)
        #pragma unroll
        for (int nt = 0; nt < 8; ++nt)
            #pragma unroll
            for (int i = 0; i < 4; ++i) acc[mt][nt][i] = 0.f;

    const int NKC = K / GBKH;

    #pragma unroll
    for (int s = 0; s < 2; ++s) {
        unsigned* As = gsm + (size_t)s * 2 * STGW2;
        unsigned* Ws = As + STGW2;
        #pragma unroll
        for (int l = 0; l < 4; ++l) {
            int row = lrow0 + l * 32;
            unsigned so = (unsigned)(row * 144 + loffh * 2);
            cp16s(smem_u32(As) + so, A + (size_t)(m0 + row) * K + s * GBKH + loffh);
            cp16s(smem_u32(Ws) + so, W + (size_t)(n0 + row) * K + s * GBKH + loffh);
        }
        asm volatile("cp.async.commit_group;");
    }

    for (int kc = 0; kc < NKC; ++kc) {
        if (kc == NKC - 1) asm volatile("cp.async.wait_group 0;");
        else               asm volatile("cp.async.wait_group 1;");
        __syncthreads();
        // all warps passed compute kc-1 -> buffer (kc+2)%3 is free
        if (kc + 2 < NKC) {
            const int s = kc + 2;
            unsigned* As = gsm + (size_t)(s % 3) * 2 * STGW2;
            unsigned* Ws = As + STGW2;
            #pragma unroll
            for (int l = 0; l < 4; ++l) {
                int row = lrow0 + l * 32;
                unsigned so = (unsigned)(row * 144 + loffh * 2);
                cp16s(smem_u32(As) + so, A + (size_t)(m0 + row) * K + s * GBKH + loffh);
                cp16s(smem_u32(Ws) + so, W + (size_t)(n0 + row) * K + s * GBKH + loffh);
            }
            asm volatile("cp.async.commit_group;");
        }

        const unsigned asb = smem_u32(gsm + (size_t)(kc % 3) * 2 * STGW2);
        const unsigned wsb = asb + STGW2 * 4;

        #pragma unroll
        for (int ks = 0; ks < 4; ++ks) {
            const int kbw = ks * 8;
            unsigned bf[8][2];
            #pragma unroll
            for (int n2 = 0; n2 < 4; ++n2) {
                unsigned ad = wsb + (unsigned)(((wn + n2 * 16) * GSTRW + kbw) * 4) + lmB;
                ldsm4(bf[2 * n2][0], bf[2 * n2][1], bf[2 * n2 + 1][0], bf[2 * n2 + 1][1], ad);
            }
            #pragma unroll
            for (int mt = 0; mt < 2; ++mt) {
                unsigned a0, a1, a2, a3;
                unsigned ad = asb + (unsigned)(((wm + mt * 16) * GSTRW + kbw) * 4) + lmA;
                ldsm4(a0, a1, a2, a3, ad);
                #pragma unroll
                for (int nt = 0; nt < 8; ++nt)
                    mma16(acc[mt][nt], a0, a1, a2, a3, bf[nt][0], bf[nt][1]);
            }
        }
    }

    #pragma unroll
    for (int mt = 0; mt < 2; ++mt) {
        #pragma unroll
        for (int nt = 0; nt < 8; ++nt) {
            int row = m0 + wm + mt * 16 + lq;
            int col = n0 + wn + nt * 8 + 2 * lr;
            float b00, b01, b10, b11;
            if (bias_rows) {
                float br = bias[row], br8 = bias[row + 8];
                b00 = br; b01 = br; b10 = br8; b11 = br8;
            } else {
                float bc0 = bias[col], bc1 = bias[col + 1];
                b00 = bc0; b01 = bc1; b10 = bc0; b11 = bc1;
            }
            float v00 = acc[mt][nt][0] + b00, v01 = acc[mt][nt][1] + b01;
            float v10 = acc[mt][nt][2] + b10, v11 = acc[mt][nt][3] + b11;
            if (out_fp32) {
                float* C = (float*)Cv;
                *(float2*)&C[(size_t)row * N + col]       = make_float2(v00, v01);
                *(float2*)&C[(size_t)(row + 8) * N + col] = make_float2(v10, v11);
            } else {
                __half* C = (__half*)Cv;
                *reinterpret_cast<unsigned*>(&C[(size_t)row * N + col])       = pack_h2(v00, v01);
                *reinterpret_cast<unsigned*>(&C[(size_t)(row + 8) * N + col]) = pack_h2(v10, v11);
            }
        }
    }
}

// ---------------- Flash attention (fp16, Q in smem, 2-stage K/V, 4 CTA/SM) ----------
#define FKW 36
#define KBUFW (64 * FKW)            // 2304 words per K/V tile
#define QBUFW (128 * FKW)           // 4608 words
#define NTT (SS/64)
#define CSC 0.1803368861f           // 0.125 * log2(e)
#define FLASH_SMEM ((4 * KBUFW + QBUFW + 2 * 32) * 4)   // 55552 B

__global__ __launch_bounds__(128, 4) void flash_h(
    const __half* __restrict__ Q, const __half* __restrict__ K,
    const __half* __restrict__ Vt, const __half* __restrict__ maskh,
    __half* __restrict__ X)
{
    extern __shared__ __align__(16) unsigned fsm[];
    unsigned* Kb = fsm;                       // [2][KBUFW]
    unsigned* Vb = fsm + 2 * KBUFW;           // [2][KBUFW]
    unsigned* Qs = fsm + 4 * KBUFW;           // [QBUFW]
    unsigned* Mb = fsm + 4 * KBUFW + QBUFW;   // [2][32]

    const int tid  = threadIdx.x;
    const int lane = tid & 31;
    const int w    = tid >> 5;
    const int lq   = lane >> 2;
    const int lr   = lane & 3;

    const int qb = blockIdx.x * 128;
    const int h  = blockIdx.y;
    const int b  = blockIdx.z;

    const __half* Kg0 = K  + (size_t)(b * SS) * DD + h * DKK;   // [key][64]
    const __half* Vg0 = Vt + (size_t)(h * DKK) * MM + b * SS;   // [d][token]
    const __half* Mg0 = maskh + b * SS;
    const __half* Qg0 = Q + (size_t)(b * SS + qb) * DD + h * DKK;

    const unsigned lmB = (((lane & 7) + ((lane >> 4) << 3)) * FKW + ((lane >> 3) & 1) * 4) * 4;
    const unsigned lmA = (((lane & 7) + (((lane >> 3) & 1) << 3)) * FKW + (lane >> 4) * 4) * 4;

    // ---- prologue: Q load + scale (by 0.125*log2e) + store to smem ----
    {
        const __half2 csc2 = __float2half2_rn(CSC);
        #pragma unroll
        for (int l = 0; l < 8; ++l) {
            int idx = tid + l * 128;
            int row = idx >> 3, ch = idx & 7;
            uint4 u = *(const uint4*)(Qg0 + (size_t)row * DD + ch * 8);
            __half2* hp = reinterpret_cast<__half2*>(&u);
            hp[0] = __hmul2(hp[0], csc2); hp[1] = __hmul2(hp[1], csc2);
            hp[2] = __hmul2(hp[2], csc2); hp[3] = __hmul2(hp[3], csc2);
            *(uint4*)(Qs + row * FKW + ch * 4) = u;
        }
    }
    // ---- prologue: K/V tile 0 + mask ----
    {
        unsigned kd = smem_u32(Kb);
        unsigned vd = smem_u32(Vb);
        #pragma unroll
        for (int l = 0; l < 4; ++l) {
            int idx = tid + l * 128;
            int row = idx >> 3, ch = idx & 7;
            unsigned so = (unsigned)(row * 144 + ch * 16);
            cp16s(kd + so, Kg0 + (size_t)row * DD + ch * 8);
            cp16s(vd + so, Vg0 + (size_t)row * MM + ch * 8);
        }
        if (tid < 8) cp16s(smem_u32(Mb) + tid * 16, Mg0 + tid * 8);
        asm volatile("cp.async.commit_group;");
    }

    const unsigned qsb = smem_u32(Qs) + (unsigned)(w * 32 * FKW * 4);
    int r0g[2];
    r0g[0] = b * SS + qb + w * 32 + lq;
    r0g[1] = r0g[0] + 16;

    float oacc[2][8][4];
    #pragma unroll
    for (int m = 0; m < 2; ++m)
        #pragma unroll
        for (int nt = 0; nt < 8; ++nt)
            #pragma unroll
            for (int i = 0; i < 4; ++i) oacc[m][nt][i] = 0.f;
    float lsum[4] = {0.f, 0.f, 0.f, 0.f};

    for (int t = 0; t < NTT; ++t) {
        asm volatile("cp.async.wait_group 0;");
        __syncthreads();
        // buffer (t+1)&1 was consumed at t-1; sync above proves all warps passed it
        if (t + 1 < NTT) {
            const int s = (t + 1) & 1;
            unsigned kd = smem_u32(Kb + s * KBUFW);
            unsigned vd = smem_u32(Vb + s * KBUFW);
            const __half* Kg = Kg0 + (size_t)((t + 1) * 64) * DD;
            const __half* Vg = Vg0 + (t + 1) * 64;
            #pragma unroll
            for (int l = 0; l < 4; ++l) {
                int idx = tid + l * 128;
                int row = idx >> 3, ch = idx & 7;
                unsigned so = (unsigned)(row * 144 + ch * 16);
                cp16s(kd + so, Kg + (size_t)row * DD + ch * 8);
                cp16s(vd + so, Vg + (size_t)row * MM + ch * 8);
            }
            if (tid < 8) cp16s(smem_u32(Mb + s * 32) + tid * 16, Mg0 + (t + 1) * 64 + tid * 8);
            asm volatile("cp.async.commit_group;");
        }

        const unsigned ksb = smem_u32(Kb + (t & 1) * KBUFW);
        const unsigned vsb = smem_u32(Vb + (t & 1) * KBUFW);
        const unsigned* Mw = Mb + (t & 1) * 32;

        #pragma unroll
        for (int hk = 0; hk < 2; ++hk) {
            // ---- S = Q K^T for keys [32hk, 32hk+32) ----
            float sacc[2][4][4];
            #pragma unroll
            for (int m = 0; m < 2; ++m)
                #pragma unroll
                for (int nt = 0; nt < 4; ++nt)
                    #pragma unroll
                    for (int i = 0; i < 4; ++i) sacc[m][nt][i] = 0.f;
            #pragma unroll
            for (int ks = 0; ks < 4; ++ks) {
                unsigned qa0[4], qa1[4];
                ldsm4(qa0[0], qa0[1], qa0[2], qa0[3], qsb + (unsigned)((ks * 8) * 4) + lmA);
                ldsm4(qa1[0], qa1[1], qa1[2], qa1[3], qsb + (unsigned)(((16 * FKW) + ks * 8) * 4) + lmA);
                #pragma unroll
                for (int n2 = 0; n2 < 2; ++n2) {
                    unsigned b00, b01, b10, b11;
                    unsigned ad = ksb + (unsigned)(((hk * 32 + n2 * 16) * FKW + ks * 8) * 4) + lmB;
                    ldsm4(b00, b01, b10, b11, ad);
                    mma16(sacc[0][2 * n2],     qa0[0], qa0[1], qa0[2], qa0[3], b00, b01);
                    mma16(sacc[1][2 * n2],     qa1[0], qa1[1], qa1[2], qa1[3], b00, b01);
                    mma16(sacc[0][2 * n2 + 1], qa0[0], qa0[1], qa0[2], qa0[3], b10, b11);
                    mma16(sacc[1][2 * n2 + 1], qa1[0], qa1[1], qa1[2], qa1[3], b10, b11);
                }
            }

            // ---- softmax: p = ex2(s) * mask (f16x2) ----
            unsigned ps[2][4][2];
            #pragma unroll
            for (int nt = 0; nt < 4; ++nt) {
                unsigned mku = Mw[hk * 16 + nt * 4 + lr];
                __half2 mk2 = *reinterpret_cast<__half2*>(&mku);
                #pragma unroll
                for (int m = 0; m < 2; ++m) {
                    unsigned p01 = ex2h2(pack_h2(sacc[m][nt][0], sacc[m][nt][1]));
                    unsigned p23 = ex2h2(pack_h2(sacc[m][nt][2], sacc[m][nt][3]));
                    __half2 hp01 = __hmul2(*reinterpret_cast<__half2*>(&p01), mk2);
                    __half2 hp23 = __hmul2(*reinterpret_cast<__half2*>(&p23), mk2);
                    float2 f01 = __half22float2(hp01);
                    float2 f23 = __half22float2(hp23);
                    lsum[2 * m]     += f01.x + f01.y;
                    lsum[2 * m + 1] += f23.x + f23.y;
                    ps[m][nt][0] = *reinterpret_cast<unsigned*>(&hp01);
                    ps[m][nt][1] = *reinterpret_cast<unsigned*>(&hp23);
                }
            }

            // ---- O += P V for this key half ----
            #pragma unroll
            for (int ks2 = 0; ks2 < 2; ++ks2) {
                #pragma unroll
                for (int n2 = 0; n2 < 4; ++n2) {
                    unsigned b00, b01, b10, b11;
                    unsigned ad = vsb + (unsigned)((n2 * 16 * FKW + hk * 16 + ks2 * 8) * 4) + lmB;
                    ldsm4(b00, b01, b10, b11, ad);
                    mma16(oacc[0][2 * n2],     ps[0][2 * ks2][0], ps[0][2 * ks2][1],
                                               ps[0][2 * ks2 + 1][0], ps[0][2 * ks2 + 1][1], b00, b01);
                    mma16(oacc[1][2 * n2],     ps[1][2 * ks2][0], ps[1][2 * ks2][1],
                                               ps[1][2 * ks2 + 1][0], ps[1][2 * ks2 + 1][1], b00, b01);
                    mma16(oacc[0][2 * n2 + 1], ps[0][2 * ks2][0], ps[0][2 * ks2][1],
                                               ps[0][2 * ks2 + 1][0], ps[0][2 * ks2 + 1][1], b10, b11);
                    mma16(oacc[1][2 * n2 + 1], ps[1][2 * ks2][0], ps[1][2 * ks2][1],
                                               ps[1][2 * ks2 + 1][0], ps[1][2 * ks2 + 1][1], b10, b11);
                }
            }
        }
    }

    #pragma unroll
    for (int i = 0; i < 4; ++i) {
        lsum[i] += __shfl_xor_sync(0xffffffffu, lsum[i], 1);
        lsum[i] += __shfl_xor_sync(0xffffffffu, lsum[i], 2);
    }

    #pragma unroll
    for (int m = 0; m < 2; ++m) {
        const float inv0 = 1.f / lsum[2 * m], inv1 = 1.f / lsum[2 * m + 1];
        __half* X0 = X + (size_t)r0g[m] * DD + h * DKK;
        __half* X8 = X + (size_t)(r0g[m] + 8) * DD + h * DKK;
        #pragma unroll
        for (int nt = 0; nt < 8; ++nt) {
            int c = nt * 8 + 2 * lr;
            *reinterpret_cast<unsigned*>(&X0[c]) = pack_h2(oacc[m][nt][0] * inv0, oacc[m][nt][1] * inv0);
            *reinterpret_cast<unsigned*>(&X8[c]) = pack_h2(oacc[m][nt][2] * inv1, oacc[m][nt][3] * inv1);
        }
    }
}

// ---------------- launch ----------------
extern "C" void kernel_launch(void* const* d_in, const int* in_sizes, int n_in,
                              void* d_out, int out_size)
{
    const float* query = (const float*)d_in[0];
    const float* key   = (const float*)d_in[1];
    const float* value = (const float*)d_in[2];
    const int*   mask  = (const int*)  d_in[3];
    const float* wq = (const float*)d_in[4];
    const float* bq = (const float*)d_in[5];
    const float* wk = (const float*)d_in[6];
    const float* bk = (const float*)d_in[7];
    const float* wv = (const float*)d_in[8];
    const float* bv = (const float*)d_in[9];
    const float* wo = (const float*)d_in[10];
    const float* bo = (const float*)d_in[11];
    float* out = (float*)d_out;

    __half *inh, *wh, *mh, *q, *k, *vt, *x;
    cudaGetSymbolAddress((void**)&inh, g_inh);
    cudaGetSymbolAddress((void**)&wh,  g_wh);
    cudaGetSymbolAddress((void**)&mh,  g_mh);
    cudaGetSymbolAddress((void**)&q,   g_q);
    cudaGetSymbolAddress((void**)&k,   g_k);
    cudaGetSymbolAddress((void**)&vt,  g_vt);
    cudaGetSymbolAddress((void**)&x,   g_x);

    cudaFuncSetAttribute(gemm_h,  cudaFuncAttributeMaxDynamicSharedMemorySize, GEMM_SMEM);
    cudaFuncSetAttribute(flash_h, cudaFuncAttributeMaxDynamicSharedMemorySize, FLASH_SMEM);

    // 0) convert inputs + weights + mask to fp16
    dim3 gpr((MM * DD / 4 + 255) / 256, 1, 8);
    tohalf<<<gpr, 256>>>(query, key, value, wq, wk, wv, wo, mask, inh, wh, mh);

    // 1) Q,K projections (fp16 out, col bias)
    dim3 gqk(DD / 128, MM / 128, 2);
    gemm_h<<<gqk, 256, GEMM_SMEM>>>(inh, inh + (size_t)MM * DD,
                                    wh,  wh  + (size_t)DD * DD,
                                    bq, bk,
                                    q, k,
                                    DD, 0, 0);

    // 2) V projection TRANSPOSED: Vt[1024x4096] = Wv @ value^T + bv (row bias)
    dim3 gvt(MM / 128, DD / 128, 1);
    gemm_h<<<gvt, 256, GEMM_SMEM>>>(wh + 2ull * DD * DD, wh + 2ull * DD * DD,
                                    inh + 2ull * MM * DD, inh + 2ull * MM * DD,
                                    bv, bv,
                                    vt, vt,
                                    MM, 0, 1);

    // 3) flash attention
    dim3 gfa(SS / 128, HH, BB);
    flash_h<<<gfa, 128, FLASH_SMEM>>>(q, k, vt, mh, x);

    // 4) output projection (fp32 out)
    dim3 go(DD / 128, MM / 128, 1);
    gemm_h<<<go, 256, GEMM_SMEM>>>(x, x,
                                   wh + 3ull * DD * DD, wh + 3ull * DD * DD,
                                   bo, bo,
                                   out, out,
                                   DD, 1, 0);
}

// round 13
// speedup vs baseline: 1.0542x; 1.0542x over previous
#include <cuda_runtime.h>
#include <cuda_fp16.h>
#include <math.h>
#include <stdint.h>

#define BB   2
#define SS   2048
#define DD   1024
#define HH   16
#define DKK  64
#define MM   (BB*SS)          // 4096
#define CSC  0.1803368861f    // 0.125 * log2(e)

// ---------------- scratch (no cudaMalloc allowed) ----------------
__device__ __half g_inh[3u*MM*DD];  // fp16 inputs (query,key,value)
__device__ __half g_wh [4u*DD*DD];  // fp16 weights (wq*CSC,wk,wv,wo)
__device__ __half g_mh [BB*SS];     // fp16 mask (0/1)
__device__ __half g_q  [MM*DD];     // Q projection (pre-scaled) [token][1024]
__device__ __half g_k  [MM*DD];     // K projection  [token][1024]
__device__ __half g_vt [MM*DD];     // V projection TRANSPOSED [1024 d][4096 token]
__device__ __half g_x  [MM*DD];     // attention out [token][1024]

// ---------------- helpers ----------------
__device__ __forceinline__ unsigned smem_u32(const void* p) {
    return (unsigned)__cvta_generic_to_shared(p);
}
__device__ __forceinline__ void cp16s(unsigned sa, const void* g) {
    asm volatile("cp.async.cg.shared.global [%0], [%1], 16;" :: "r"(sa), "l"(g));
}
__device__ __forceinline__ void mma16(float d[4],
                                      unsigned a0, unsigned a1, unsigned a2, unsigned a3,
                                      unsigned b0, unsigned b1) {
    asm volatile(
        "mma.sync.aligned.m16n8k16.row.col.f32.f16.f16.f32 "
        "{%0,%1,%2,%3}, {%4,%5,%6,%7}, {%8,%9}, {%0,%1,%2,%3};"
        : "+f"(d[0]), "+f"(d[1]), "+f"(d[2]), "+f"(d[3])
        : "r"(a0), "r"(a1), "r"(a2), "r"(a3), "r"(b0), "r"(b1));
}
__device__ __forceinline__ void ldsm4(unsigned& r0, unsigned& r1, unsigned& r2, unsigned& r3,
                                      unsigned a) {
    asm volatile("ldmatrix.sync.aligned.m8n8.x4.shared.b16 {%0,%1,%2,%3}, [%4];"
                 : "=r"(r0), "=r"(r1), "=r"(r2), "=r"(r3) : "r"(a));
}
__device__ __forceinline__ unsigned pack_h2(float a, float b) {
    __half2 h = __floats2half2_rn(a, b);
    return *reinterpret_cast<unsigned*>(&h);
}
__device__ __forceinline__ unsigned ex2h2(unsigned x) {
    unsigned r;
    asm("ex2.approx.f16x2 %0, %1;" : "=r"(r) : "r"(x));
    return r;
}

// ---------------- fp32 -> fp16 conversion pass (wq pre-scaled by CSC) ----------------
__global__ void tohalf(const float* __restrict__ q, const float* __restrict__ k,
                       const float* __restrict__ v,
                       const float* __restrict__ wq, const float* __restrict__ wk,
                       const float* __restrict__ wv, const float* __restrict__ wo,
                       const int* __restrict__ mask,
                       __half* __restrict__ dinh, __half* __restrict__ dwh,
                       __half* __restrict__ dmh)
{
    const int z = blockIdx.z;
    int i = (blockIdx.x * blockDim.x + threadIdx.x) * 4;
    if (z == 7) {
        if (i < BB * SS) {
            int4 m = *(const int4*)(mask + i);
            __half h[4];
            h[0] = __int2half_rn(m.x); h[1] = __int2half_rn(m.y);
            h[2] = __int2half_rn(m.z); h[3] = __int2half_rn(m.w);
            *(uint2*)(dmh + i) = *(uint2*)h;
        }
        return;
    }
    const float* src; __half* dst; int n;
    float sc = 1.0f;
    if (z < 3) {
        src = (z == 0) ? q : (z == 1) ? k : v;
        dst = dinh + (size_t)z * MM * DD;  n = MM * DD;
    } else {
        src = (z == 3) ? wq : (z == 4) ? wk : (z == 5) ? wv : wo;
        dst = dwh + (size_t)(z - 3) * DD * DD;  n = DD * DD;
        if (z == 3) sc = CSC;   // fold softmax scale into wq
    }
    if (i < n) {
        float4 t = *(const float4*)(src + i);
        uint2 u;
        u.x = pack_h2(t.x * sc, t.y * sc);
        u.y = pack_h2(t.z * sc, t.w * sc);
        *(uint2*)(dst + i) = u;
    }
}

// ---------------- GEMM (fp16 mma + ldmatrix, 3-stage cp.async, 1 sync/chunk) --------
#define GBKH 64
#define GSTRW 36
#define STGW2 (128 * GSTRW)
#define GEMM_SMEM (3 * 2 * STGW2 * 4)

__global__ __launch_bounds__(256, 2) void gemm_h(
    const __half* __restrict__ A0, const __half* __restrict__ A1,
    const __half* __restrict__ W0, const __half* __restrict__ W1,
    const float* __restrict__ b0p, const float* __restrict__ b1p,
    void* __restrict__ C0v, void* __restrict__ C1v,
    int N, int out_fp32, int bias_rows, float bsc0, float bsc1)
{
    const int z = blockIdx.z;
    const __half* __restrict__ A    = z ? A1 : A0;
    const __half* __restrict__ W    = z ? W1 : W0;
    const float*  __restrict__ bias = z ? b1p : b0p;
    const float bsc = z ? bsc1 : bsc0;
    void* Cv = z ? C1v : C0v;
    const int K = DD;

    extern __shared__ __align__(16) unsigned gsm[];

    const int tid  = threadIdx.x;
    const int lane = tid & 31;
    const int wid  = tid >> 5;
    const int wm   = (wid & 3) * 32;
    const int wn   = (wid >> 2) * 64;
    const int m0   = blockIdx.y * 128;
    const int n0   = blockIdx.x * 128;
    const int lq   = lane >> 2;
    const int lr   = lane & 3;

    const int lrow0 = tid >> 3;
    const int loffh = (tid & 7) * 8;

    const unsigned lmB = (((lane & 7) + ((lane >> 4) << 3)) * GSTRW + ((lane >> 3) & 1) * 4) * 4;
    const unsigned lmA = (((lane & 7) + (((lane >> 3) & 1) << 3)) * GSTRW + (lane >> 4) * 4) * 4;

    float acc[2][8][4];
    #pragma unroll
    for (int mt = 0; mt < 2; ++mt)
        #pragma unroll
        for (int nt = 0; nt < 8; ++nt)
            #pragma unroll
            for (int i = 0; i < 4; ++i) acc[mt][nt][i] = 0.f;

    const int NKC = K / GBKH;

    #pragma unroll
    for (int s = 0; s < 2; ++s) {
        unsigned* As = gsm + (size_t)s * 2 * STGW2;
        unsigned* Ws = As + STGW2;
        #pragma unroll
        for (int l = 0; l < 4; ++l) {
            int row = lrow0 + l * 32;
            unsigned so = (unsigned)(row * 144 + loffh * 2);
            cp16s(smem_u32(As) + so, A + (size_t)(m0 + row) * K + s * GBKH + loffh);
            cp16s(smem_u32(Ws) + so, W + (size_t)(n0 + row) * K + s * GBKH + loffh);
        }
        asm volatile("cp.async.commit_group;");
    }

    for (int kc = 0; kc < NKC; ++kc) {
        if (kc == NKC - 1) asm volatile("cp.async.wait_group 0;");
        else               asm volatile("cp.async.wait_group 1;");
        __syncthreads();
        if (kc + 2 < NKC) {
            const int s = kc + 2;
            unsigned* As = gsm + (size_t)(s % 3) * 2 * STGW2;
            unsigned* Ws = As + STGW2;
            #pragma unroll
            for (int l = 0; l < 4; ++l) {
                int row = lrow0 + l * 32;
                unsigned so = (unsigned)(row * 144 + loffh * 2);
                cp16s(smem_u32(As) + so, A + (size_t)(m0 + row) * K + s * GBKH + loffh);
                cp16s(smem_u32(Ws) + so, W + (size_t)(n0 + row) * K + s * GBKH + loffh);
            }
            asm volatile("cp.async.commit_group;");
        }

        const unsigned asb = smem_u32(gsm + (size_t)(kc % 3) * 2 * STGW2);
        const unsigned wsb = asb + STGW2 * 4;

        #pragma unroll
        for (int ks = 0; ks < 4; ++ks) {
            const int kbw = ks * 8;
            unsigned bf[8][2];
            #pragma unroll
            for (int n2 = 0; n2 < 4; ++n2) {
                unsigned ad = wsb + (unsigned)(((wn + n2 * 16) * GSTRW + kbw) * 4) + lmB;
                ldsm4(bf[2 * n2][0], bf[2 * n2][1], bf[2 * n2 + 1][0], bf[2 * n2 + 1][1], ad);
            }
            #pragma unroll
            for (int mt = 0; mt < 2; ++mt) {
                unsigned a0, a1, a2, a3;
                unsigned ad = asb + (unsigned)(((wm + mt * 16) * GSTRW + kbw) * 4) + lmA;
                ldsm4(a0, a1, a2, a3, ad);
                #pragma unroll
                for (int nt = 0; nt < 8; ++nt)
                    mma16(acc[mt][nt], a0, a1, a2, a3, bf[nt][0], bf[nt][1]);
            }
        }
    }

    #pragma unroll
    for (int mt = 0; mt < 2; ++mt) {
        #pragma unroll
        for (int nt = 0; nt < 8; ++nt) {
            int row = m0 + wm + mt * 16 + lq;
            int col = n0 + wn + nt * 8 + 2 * lr;
            float b00, b01, b10, b11;
            if (bias_rows) {
                float br = bias[row] * bsc, br8 = bias[row + 8] * bsc;
                b00 = br; b01 = br; b10 = br8; b11 = br8;
            } else {
                float bc0 = bias[col] * bsc, bc1 = bias[col + 1] * bsc;
                b00 = bc0; b01 = bc1; b10 = bc0; b11 = bc1;
            }
            float v00 = acc[mt][nt][0] + b00, v01 = acc[mt][nt][1] + b01;
            float v10 = acc[mt][nt][2] + b10, v11 = acc[mt][nt][3] + b11;
            if (out_fp32) {
                float* C = (float*)Cv;
                *(float2*)&C[(size_t)row * N + col]       = make_float2(v00, v01);
                *(float2*)&C[(size_t)(row + 8) * N + col] = make_float2(v10, v11);
            } else {
                __half* C = (__half*)Cv;
                *reinterpret_cast<unsigned*>(&C[(size_t)row * N + col])       = pack_h2(v00, v01);
                *reinterpret_cast<unsigned*>(&C[(size_t)(row + 8) * N + col]) = pack_h2(v10, v11);
            }
        }
    }
}

// ---------------- Flash attention (fp16, Q in regs, 128-key tiles, 2-stage) ---------
// Block: 128 q rows, 4 warps x 32 rows (2 m16 tiles). Key tile = 128, four 32-key quarters.
#define FKW 36                       // K smem: 128 rows x (64 halves + pad) -> 36 words
#define FVW 68                       // V smem: 64 d-rows x (128 halves + pad) -> 68 words
#define KBUFW (128 * FKW)            // 4608 words
#define VBUFW (64 * FVW)             // 4352 words
#define NT2 (SS/128)                 // 16 tiles
#define FLASH_SMEM ((2*KBUFW + 2*VBUFW + 2*64) * 4)   // 72192 B

__global__ __launch_bounds__(128) void flash_h(
    const __half* __restrict__ Q, const __half* __restrict__ K,
    const __half* __restrict__ Vt, const __half* __restrict__ maskh,
    __half* __restrict__ X)
{
    extern __shared__ __align__(16) unsigned fsm[];
    unsigned* Kb = fsm;                         // [2][KBUFW]
    unsigned* Vb = fsm + 2 * KBUFW;             // [2][VBUFW]
    unsigned* Mb = fsm + 2 * KBUFW + 2 * VBUFW; // [2][64]

    const int tid  = threadIdx.x;
    const int lane = tid & 31;
    const int w    = tid >> 5;
    const int lq   = lane >> 2;
    const int lr   = lane & 3;

    const int qb = blockIdx.x * 128;
    const int h  = blockIdx.y;
    const int b  = blockIdx.z;

    const __half* Kg0 = K  + (size_t)(b * SS) * DD + h * DKK;   // [key][64]
    const __half* Vg0 = Vt + (size_t)(h * DKK) * MM + b * SS;   // [d][token]
    const __half* Mg0 = maskh + b * SS;

    const unsigned lmBk = (((lane & 7) + ((lane >> 4) << 3)) * FKW + ((lane >> 3) & 1) * 4) * 4;
    const unsigned lmBv = (((lane & 7) + ((lane >> 4) << 3)) * FVW + ((lane >> 3) & 1) * 4) * 4;

    // ---- prologue: K/V/mask tile 0 ----
    {
        unsigned kd = smem_u32(Kb);
        unsigned vd = smem_u32(Vb);
        #pragma unroll
        for (int l = 0; l < 8; ++l) {
            int idx = tid + l * 128;
            int krow = idx >> 3, kch = idx & 7;
            cp16s(kd + (unsigned)(krow * 144 + kch * 16), Kg0 + (size_t)krow * DD + kch * 8);
            int vrow = idx >> 4, vch = idx & 15;
            if (l < 8) cp16s(vd + (unsigned)(vrow * 272 + vch * 16), Vg0 + (size_t)vrow * MM + vch * 8);
        }
        if (tid < 16) cp16s(smem_u32(Mb) + tid * 16, Mg0 + tid * 8);
        asm volatile("cp.async.commit_group;");
    }

    // ---- Q fragments (g_q is pre-scaled by 0.125*log2e) ----
    int r0g[2];
    unsigned qf[2][4][4];
    #pragma unroll
    for (int m = 0; m < 2; ++m) {
        r0g[m] = b * SS + qb + w * 32 + m * 16 + lq;
        const unsigned* Qw  = (const unsigned*)(Q + (size_t)r0g[m] * DD + h * DKK);
        const unsigned* Qw8 = (const unsigned*)(Q + (size_t)(r0g[m] + 8) * DD + h * DKK);
        #pragma unroll
        for (int ks = 0; ks < 4; ++ks) {
            qf[m][ks][0] = Qw [8 * ks + lr];
            qf[m][ks][1] = Qw8[8 * ks + lr];
            qf[m][ks][2] = Qw [8 * ks + 4 + lr];
            qf[m][ks][3] = Qw8[8 * ks + 4 + lr];
        }
    }

    float oacc[2][8][4];
    #pragma unroll
    for (int m = 0; m < 2; ++m)
        #pragma unroll
        for (int nt = 0; nt < 8; ++nt)
            #pragma unroll
            for (int i = 0; i < 4; ++i) oacc[m][nt][i] = 0.f;
    float lsum[4] = {0.f, 0.f, 0.f, 0.f};

    for (int t = 0; t < NT2; ++t) {
        asm volatile("cp.async.wait_group 0;");
        __syncthreads();
        // buffer (t+1)&1 was consumed at t-1; sync proves all warps passed it
        if (t + 1 < NT2) {
            const int s = (t + 1) & 1;
            unsigned kd = smem_u32(Kb + s * KBUFW);
            unsigned vd = smem_u32(Vb + s * VBUFW);
            const __half* Kg = Kg0 + (size_t)((t + 1) * 128) * DD;
            const __half* Vg = Vg0 + (t + 1) * 128;
            #pragma unroll
            for (int l = 0; l < 8; ++l) {
                int idx = tid + l * 128;
                int krow = idx >> 3, kch = idx & 7;
                cp16s(kd + (unsigned)(krow * 144 + kch * 16), Kg + (size_t)krow * DD + kch * 8);
                int vrow = idx >> 4, vch = idx & 15;
                cp16s(vd + (unsigned)(vrow * 272 + vch * 16), Vg + (size_t)vrow * MM + vch * 8);
            }
            if (tid < 16) cp16s(smem_u32(Mb + s * 64) + tid * 16, Mg0 + (t + 1) * 128 + tid * 8);
            asm volatile("cp.async.commit_group;");
        }

        const unsigned ksb = smem_u32(Kb + (t & 1) * KBUFW);
        const unsigned vsb = smem_u32(Vb + (t & 1) * VBUFW);
        const unsigned* Mw = Mb + (t & 1) * 64;

        #pragma unroll
        for (int hk = 0; hk < 4; ++hk) {   // four 32-key quarters
            // ---- S = Q K^T for keys [32hk, 32hk+32) ----
            float sacc[2][4][4];
            #pragma unroll
            for (int m = 0; m < 2; ++m)
                #pragma unroll
                for (int nt = 0; nt < 4; ++nt)
                    #pragma unroll
                    for (int i = 0; i < 4; ++i) sacc[m][nt][i] = 0.f;
            #pragma unroll
            for (int ks = 0; ks < 4; ++ks) {
                #pragma unroll
                for (int n2 = 0; n2 < 2; ++n2) {
                    unsigned b00, b01, b10, b11;
                    unsigned ad = ksb + (unsigned)(((hk * 32 + n2 * 16) * FKW + ks * 8) * 4) + lmBk;
                    ldsm4(b00, b01, b10, b11, ad);
                    mma16(sacc[0][2 * n2],     qf[0][ks][0], qf[0][ks][1], qf[0][ks][2], qf[0][ks][3], b00, b01);
                    mma16(sacc[1][2 * n2],     qf[1][ks][0], qf[1][ks][1], qf[1][ks][2], qf[1][ks][3], b00, b01);
                    mma16(sacc[0][2 * n2 + 1], qf[0][ks][0], qf[0][ks][1], qf[0][ks][2], qf[0][ks][3], b10, b11);
                    mma16(sacc[1][2 * n2 + 1], qf[1][ks][0], qf[1][ks][1], qf[1][ks][2], qf[1][ks][3], b10, b11);
                }
            }

            // ---- softmax: p = ex2(s) * mask (f16x2) ----
            unsigned ps[2][4][2];
            #pragma unroll
            for (int nt = 0; nt < 4; ++nt) {
                unsigned mku = Mw[hk * 16 + nt * 4 + lr];
                __half2 mk2 = *reinterpret_cast<__half2*>(&mku);
                #pragma unroll
                for (int m = 0; m < 2; ++m) {
                    unsigned p01 = ex2h2(pack_h2(sacc[m][nt][0], sacc[m][nt][1]));
                    unsigned p23 = ex2h2(pack_h2(sacc[m][nt][2], sacc[m][nt][3]));
                    __half2 hp01 = __hmul2(*reinterpret_cast<__half2*>(&p01), mk2);
                    __half2 hp23 = __hmul2(*reinterpret_cast<__half2*>(&p23), mk2);
                    float2 f01 = __half22float2(hp01);
                    float2 f23 = __half22float2(hp23);
                    lsum[2 * m]     += f01.x + f01.y;
                    lsum[2 * m + 1] += f23.x + f23.y;
                    ps[m][nt][0] = *reinterpret_cast<unsigned*>(&hp01);
                    ps[m][nt][1] = *reinterpret_cast<unsigned*>(&hp23);
                }
            }

            // ---- O += P V for this quarter (keys hk*32 .. +32) ----
            #pragma unroll
            for (int ks2 = 0; ks2 < 2; ++ks2) {
                #pragma unroll
                for (int n2 = 0; n2 < 4; ++n2) {
                    unsigned b00, b01, b10, b11;
                    unsigned ad = vsb + (unsigned)((n2 * 16 * FVW + hk * 16 + ks2 * 8) * 4) + lmBv;
                    ldsm4(b00, b01, b10, b11, ad);
                    mma16(oacc[0][2 * n2],     ps[0][2 * ks2][0], ps[0][2 * ks2][1],
                                               ps[0][2 * ks2 + 1][0], ps[0][2 * ks2 + 1][1], b00, b01);
                    mma16(oacc[1][2 * n2],     ps[1][2 * ks2][0], ps[1][2 * ks2][1],
                                               ps[1][2 * ks2 + 1][0], ps[1][2 * ks2 + 1][1], b00, b01);
                    mma16(oacc[0][2 * n2 + 1], ps[0][2 * ks2][0], ps[0][2 * ks2][1],
                                               ps[0][2 * ks2 + 1][0], ps[0][2 * ks2 + 1][1], b10, b11);
                    mma16(oacc[1][2 * n2 + 1], ps[1][2 * ks2][0], ps[1][2 * ks2][1],
                                               ps[1][2 * ks2 + 1][0], ps[1][2 * ks2 + 1][1], b10, b11);
                }
            }
        }
    }

    #pragma unroll
    for (int i = 0; i < 4; ++i) {
        lsum[i] += __shfl_xor_sync(0xffffffffu, lsum[i], 1);
        lsum[i] += __shfl_xor_sync(0xffffffffu, lsum[i], 2);
    }

    #pragma unroll
    for (int m = 0; m < 2; ++m) {
        const float inv0 = 1.f / lsum[2 * m], inv1 = 1.f / lsum[2 * m + 1];
        __half* X0 = X + (size_t)r0g[m] * DD + h * DKK;
        __half* X8 = X + (size_t)(r0g[m] + 8) * DD + h * DKK;
        #pragma unroll
        for (int nt = 0; nt < 8; ++nt) {
            int c = nt * 8 + 2 * lr;
            *reinterpret_cast<unsigned*>(&X0[c]) = pack_h2(oacc[m][nt][0] * inv0, oacc[m][nt][1] * inv0);
            *reinterpret_cast<unsigned*>(&X8[c]) = pack_h2(oacc[m][nt][2] * inv1, oacc[m][nt][3] * inv1);
        }
    }
}

// ---------------- launch ----------------
extern "C" void kernel_launch(void* const* d_in, const int* in_sizes, int n_in,
                              void* d_out, int out_size)
{
    const float* query = (const float*)d_in[0];
    const float* key   = (const float*)d_in[1];
    const float* value = (const float*)d_in[2];
    const int*   mask  = (const int*)  d_in[3];
    const float* wq = (const float*)d_in[4];
    const float* bq = (const float*)d_in[5];
    const float* wk = (const float*)d_in[6];
    const float* bk = (const float*)d_in[7];
    const float* wv = (const float*)d_in[8];
    const float* bv = (const float*)d_in[9];
    const float* wo = (const float*)d_in[10];
    const float* bo = (const float*)d_in[11];
    float* out = (float*)d_out;

    __half *inh, *wh, *mh, *q, *k, *vt, *x;
    cudaGetSymbolAddress((void**)&inh, g_inh);
    cudaGetSymbolAddress((void**)&wh,  g_wh);
    cudaGetSymbolAddress((void**)&mh,  g_mh);
    cudaGetSymbolAddress((void**)&q,   g_q);
    cudaGetSymbolAddress((void**)&k,   g_k);
    cudaGetSymbolAddress((void**)&vt,  g_vt);
    cudaGetSymbolAddress((void**)&x,   g_x);

    cudaFuncSetAttribute(gemm_h,  cudaFuncAttributeMaxDynamicSharedMemorySize, GEMM_SMEM);
    cudaFuncSetAttribute(flash_h, cudaFuncAttributeMaxDynamicSharedMemorySize, FLASH_SMEM);

    // 0) convert inputs + weights (wq pre-scaled by CSC) + mask to fp16
    dim3 gpr((MM * DD / 4 + 255) / 256, 1, 8);
    tohalf<<<gpr, 256>>>(query, key, value, wq, wk, wv, wo, mask, inh, wh, mh);

    // 1) Q,K projections (fp16 out, col bias; Q bias scaled by CSC to match wq)
    dim3 gqk(DD / 128, MM / 128, 2);
    gemm_h<<<gqk, 256, GEMM_SMEM>>>(inh, inh + (size_t)MM * DD,
                                    wh,  wh  + (size_t)DD * DD,
                                    bq, bk,
                                    q, k,
                                    DD, 0, 0, CSC, 1.0f);

    // 2) V projection TRANSPOSED: Vt[1024x4096] = Wv @ value^T + bv (row bias)
    dim3 gvt(MM / 128, DD / 128, 1);
    gemm_h<<<gvt, 256, GEMM_SMEM>>>(wh + 2ull * DD * DD, wh + 2ull * DD * DD,
                                    inh + 2ull * MM * DD, inh + 2ull * MM * DD,
                                    bv, bv,
                                    vt, vt,
                                    MM, 0, 1, 1.0f, 1.0f);

    // 3) flash attention (128-key tiles, 2-stage)
    dim3 gfa(SS / 128, HH, BB);
    flash_h<<<gfa, 128, FLASH_SMEM>>>(q, k, vt, mh, x);

    // 4) output projection (fp32 out)
    dim3 go(DD / 128, MM / 128, 1);
    gemm_h<<<go, 256, GEMM_SMEM>>>(x, x,
                                   wh + 3ull * DD * DD, wh + 3ull * DD * DD,
                                   bo, bo,
                                   out, out,
                                   DD, 1, 0, 1.0f, 1.0f);
}

// round 14
// speedup vs baseline: 1.0816x; 1.0260x over previous
#include <cuda_runtime.h>
#include <cuda_fp16.h>
#include <math.h>
#include <stdint.h>

#define BB   2
#define SS   2048
#define DD   1024
#define HH   16
#define DKK  64
#define MM   (BB*SS)          // 4096
#define CSC  0.1803368861f    // 0.125 * log2(e)

// ---------------- scratch (no cudaMalloc allowed) ----------------
__device__ __half g_inh[3u*MM*DD];  // fp16 inputs (query,key,value)
__device__ __half g_wh [4u*DD*DD];  // fp16 weights (wq*CSC,wk,wv,wo)
__device__ __half g_mh [BB*SS];     // fp16 mask (0/1)
__device__ __half g_q  [MM*DD];     // Q projection (pre-scaled) [token][1024]
__device__ __half g_k  [MM*DD];     // K projection  [token][1024]
__device__ __half g_vt [MM*DD];     // V projection TRANSPOSED [1024 d][4096 token]
__device__ __half g_x  [MM*DD];     // attention out [token][1024]

// ---------------- helpers ----------------
__device__ __forceinline__ unsigned smem_u32(const void* p) {
    return (unsigned)__cvta_generic_to_shared(p);
}
__device__ __forceinline__ void cp16s(unsigned sa, const void* g) {
    asm volatile("cp.async.cg.shared.global [%0], [%1], 16;" :: "r"(sa), "l"(g));
}
__device__ __forceinline__ void mma16(float d[4],
                                      unsigned a0, unsigned a1, unsigned a2, unsigned a3,
                                      unsigned b0, unsigned b1) {
    asm volatile(
        "mma.sync.aligned.m16n8k16.row.col.f32.f16.f16.f32 "
        "{%0,%1,%2,%3}, {%4,%5,%6,%7}, {%8,%9}, {%0,%1,%2,%3};"
        : "+f"(d[0]), "+f"(d[1]), "+f"(d[2]), "+f"(d[3])
        : "r"(a0), "r"(a1), "r"(a2), "r"(a3), "r"(b0), "r"(b1));
}
__device__ __forceinline__ void ldsm4(unsigned& r0, unsigned& r1, unsigned& r2, unsigned& r3,
                                      unsigned a) {
    asm volatile("ldmatrix.sync.aligned.m8n8.x4.shared.b16 {%0,%1,%2,%3}, [%4];"
                 : "=r"(r0), "=r"(r1), "=r"(r2), "=r"(r3) : "r"(a));
}
__device__ __forceinline__ unsigned pack_h2(float a, float b) {
    __half2 h = __floats2half2_rn(a, b);
    return *reinterpret_cast<unsigned*>(&h);
}
__device__ __forceinline__ unsigned ex2h2(unsigned x) {
    unsigned r;
    asm("ex2.approx.f16x2 %0, %1;" : "=r"(r) : "r"(x));
    return r;
}

// ---------------- fp32 -> fp16 conversion pass (wq pre-scaled by CSC) ----------------
__global__ void tohalf(const float* __restrict__ q, const float* __restrict__ k,
                       const float* __restrict__ v,
                       const float* __restrict__ wq, const float* __restrict__ wk,
                       const float* __restrict__ wv, const float* __restrict__ wo,
                       const int* __restrict__ mask,
                       __half* __restrict__ dinh, __half* __restrict__ dwh,
                       __half* __restrict__ dmh)
{
    const int z = blockIdx.z;
    int i = (blockIdx.x * blockDim.x + threadIdx.x) * 4;
    if (z == 7) {
        if (i < BB * SS) {
            int4 m = *(const int4*)(mask + i);
            __half h[4];
            h[0] = __int2half_rn(m.x); h[1] = __int2half_rn(m.y);
            h[2] = __int2half_rn(m.z); h[3] = __int2half_rn(m.w);
            *(uint2*)(dmh + i) = *(uint2*)h;
        }
        return;
    }
    const float* src; __half* dst; int n;
    float sc = 1.0f;
    if (z < 3) {
        src = (z == 0) ? q : (z == 1) ? k : v;
        dst = dinh + (size_t)z * MM * DD;  n = MM * DD;
    } else {
        src = (z == 3) ? wq : (z == 4) ? wk : (z == 5) ? wv : wo;
        dst = dwh + (size_t)(z - 3) * DD * DD;  n = DD * DD;
        if (z == 3) sc = CSC;   // fold softmax scale into wq
    }
    if (i < n) {
        float4 t = *(const float4*)(src + i);
        uint2 u;
        u.x = pack_h2(t.x * sc, t.y * sc);
        u.y = pack_h2(t.z * sc, t.w * sc);
        *(uint2*)(dst + i) = u;
    }
}

// ---------------- GEMM (fp16 mma + ldmatrix, 3-stage cp.async, 1 sync/chunk) --------
#define GBKH 64
#define GSTRW 36
#define STGW2 (128 * GSTRW)
#define GEMM_SMEM (3 * 2 * STGW2 * 4)

__global__ __launch_bounds__(256, 2) void gemm_h(
    const __half* __restrict__ A0, const __half* __restrict__ A1,
    const __half* __restrict__ W0, const __half* __restrict__ W1,
    const float* __restrict__ b0p, const float* __restrict__ b1p,
    void* __restrict__ C0v, void* __restrict__ C1v,
    int N, int out_fp32, int bias_rows, float bsc0, float bsc1)
{
    const int z = blockIdx.z;
    const __half* __restrict__ A    = z ? A1 : A0;
    const __half* __restrict__ W    = z ? W1 : W0;
    const float*  __restrict__ bias = z ? b1p : b0p;
    const float bsc = z ? bsc1 : bsc0;
    void* Cv = z ? C1v : C0v;
    const int K = DD;

    extern __shared__ __align__(16) unsigned gsm[];

    const int tid  = threadIdx.x;
    const int lane = tid & 31;
    const int wid  = tid >> 5;
    const int wm   = (wid & 3) * 32;
    const int wn   = (wid >> 2) * 64;
    const int m0   = blockIdx.y * 128;
    const int n0   = blockIdx.x * 128;
    const int lq   = lane >> 2;
    const int lr   = lane & 3;

    const int lrow0 = tid >> 3;
    const int loffh = (tid & 7) * 8;

    const unsigned lmB = (((lane & 7) + ((lane >> 4) << 3)) * GSTRW + ((lane >> 3) & 1) * 4) * 4;
    const unsigned lmA = (((lane & 7) + (((lane >> 3) & 1) << 3)) * GSTRW + (lane >> 4) * 4) * 4;

    float acc[2][8][4];
    #pragma unroll
    for (int mt = 0; mt < 2; ++mt)
        #pragma unroll
        for (int nt = 0; nt < 8; ++nt)
            #pragma unroll
            for (int i = 0; i < 4; ++i) acc[mt][nt][i] = 0.f;

    const int NKC = K / GBKH;

    #pragma unroll
    for (int s = 0; s < 2; ++s) {
        unsigned* As = gsm + (size_t)s * 2 * STGW2;
        unsigned* Ws = As + STGW2;
        #pragma unroll
        for (int l = 0; l < 4; ++l) {
            int row = lrow0 + l * 32;
            unsigned so = (unsigned)(row * 144 + loffh * 2);
            cp16s(smem_u32(As) + so, A + (size_t)(m0 + row) * K + s * GBKH + loffh);
            cp16s(smem_u32(Ws) + so, W + (size_t)(n0 + row) * K + s * GBKH + loffh);
        }
        asm volatile("cp.async.commit_group;");
    }

    for (int kc = 0; kc < NKC; ++kc) {
        if (kc == NKC - 1) asm volatile("cp.async.wait_group 0;");
        else               asm volatile("cp.async.wait_group 1;");
        __syncthreads();
        if (kc + 2 < NKC) {
            const int s = kc + 2;
            unsigned* As = gsm + (size_t)(s % 3) * 2 * STGW2;
            unsigned* Ws = As + STGW2;
            #pragma unroll
            for (int l = 0; l < 4; ++l) {
                int row = lrow0 + l * 32;
                unsigned so = (unsigned)(row * 144 + loffh * 2);
                cp16s(smem_u32(As) + so, A + (size_t)(m0 + row) * K + s * GBKH + loffh);
                cp16s(smem_u32(Ws) + so, W + (size_t)(n0 + row) * K + s * GBKH + loffh);
            }
            asm volatile("cp.async.commit_group;");
        }

        const unsigned asb = smem_u32(gsm + (size_t)(kc % 3) * 2 * STGW2);
        const unsigned wsb = asb + STGW2 * 4;

        #pragma unroll
        for (int ks = 0; ks < 4; ++ks) {
            const int kbw = ks * 8;
            unsigned bf[8][2];
            #pragma unroll
            for (int n2 = 0; n2 < 4; ++n2) {
                unsigned ad = wsb + (unsigned)(((wn + n2 * 16) * GSTRW + kbw) * 4) + lmB;
                ldsm4(bf[2 * n2][0], bf[2 * n2][1], bf[2 * n2 + 1][0], bf[2 * n2 + 1][1], ad);
            }
            #pragma unroll
            for (int mt = 0; mt < 2; ++mt) {
                unsigned a0, a1, a2, a3;
                unsigned ad = asb + (unsigned)(((wm + mt * 16) * GSTRW + kbw) * 4) + lmA;
                ldsm4(a0, a1, a2, a3, ad);
                #pragma unroll
                for (int nt = 0; nt < 8; ++nt)
                    mma16(acc[mt][nt], a0, a1, a2, a3, bf[nt][0], bf[nt][1]);
            }
        }
    }

    #pragma unroll
    for (int mt = 0; mt < 2; ++mt) {
        #pragma unroll
        for (int nt = 0; nt < 8; ++nt) {
            int row = m0 + wm + mt * 16 + lq;
            int col = n0 + wn + nt * 8 + 2 * lr;
            float b00, b01, b10, b11;
            if (bias_rows) {
                float br = bias[row] * bsc, br8 = bias[row + 8] * bsc;
                b00 = br; b01 = br; b10 = br8; b11 = br8;
            } else {
                float bc0 = bias[col] * bsc, bc1 = bias[col + 1] * bsc;
                b00 = bc0; b01 = bc1; b10 = bc0; b11 = bc1;
            }
            float v00 = acc[mt][nt][0] + b00, v01 = acc[mt][nt][1] + b01;
            float v10 = acc[mt][nt][2] + b10, v11 = acc[mt][nt][3] + b11;
            if (out_fp32) {
                float* C = (float*)Cv;
                *(float2*)&C[(size_t)row * N + col]       = make_float2(v00, v01);
                *(float2*)&C[(size_t)(row + 8) * N + col] = make_float2(v10, v11);
            } else {
                __half* C = (__half*)Cv;
                *reinterpret_cast<unsigned*>(&C[(size_t)row * N + col])       = pack_h2(v00, v01);
                *reinterpret_cast<unsigned*>(&C[(size_t)(row + 8) * N + col]) = pack_h2(v10, v11);
            }
        }
    }
}

// ---------------- Flash attention (fp16, 128-key tiles, MMA-computed row sums) ------
// Block: 128 q rows, 4 warps x 32 rows (2 m16 tiles). Key tile = 128, four 32-key quarters.
// l = P @ ones computed by an extra MMA with constant ones B-fragment (no ldsm, no cvt).
#define FKW 36                       // K smem: 128 rows x (64 halves + pad) -> 36 words
#define FVW 68                       // V smem: 64 d-rows x (128 halves + pad) -> 68 words
#define KBUFW (128 * FKW)            // 4608 words
#define VBUFW (64 * FVW)             // 4352 words
#define NT2 (SS/128)                 // 16 tiles
#define ONES 0x3C003C00u             // (1.0h, 1.0h)
#define FLASH_SMEM ((2*KBUFW + 2*VBUFW + 2*64) * 4)   // 72192 B

__global__ __launch_bounds__(128) void flash_h(
    const __half* __restrict__ Q, const __half* __restrict__ K,
    const __half* __restrict__ Vt, const __half* __restrict__ maskh,
    __half* __restrict__ X)
{
    extern __shared__ __align__(16) unsigned fsm[];
    unsigned* Kb = fsm;                         // [2][KBUFW]
    unsigned* Vb = fsm + 2 * KBUFW;             // [2][VBUFW]
    unsigned* Mb = fsm + 2 * KBUFW + 2 * VBUFW; // [2][64]

    const int tid  = threadIdx.x;
    const int lane = tid & 31;
    const int w    = tid >> 5;
    const int lq   = lane >> 2;
    const int lr   = lane & 3;

    const int qb = blockIdx.x * 128;
    const int h  = blockIdx.y;
    const int b  = blockIdx.z;

    const __half* Kg0 = K  + (size_t)(b * SS) * DD + h * DKK;   // [key][64]
    const __half* Vg0 = Vt + (size_t)(h * DKK) * MM + b * SS;   // [d][token]
    const __half* Mg0 = maskh + b * SS;

    const unsigned lmBk = (((lane & 7) + ((lane >> 4) << 3)) * FKW + ((lane >> 3) & 1) * 4) * 4;
    const unsigned lmBv = (((lane & 7) + ((lane >> 4) << 3)) * FVW + ((lane >> 3) & 1) * 4) * 4;

    // ---- prologue: K/V/mask tile 0 ----
    {
        unsigned kd = smem_u32(Kb);
        unsigned vd = smem_u32(Vb);
        #pragma unroll
        for (int l = 0; l < 8; ++l) {
            int idx = tid + l * 128;
            int krow = idx >> 3, kch = idx & 7;
            cp16s(kd + (unsigned)(krow * 144 + kch * 16), Kg0 + (size_t)krow * DD + kch * 8);
            int vrow = idx >> 4, vch = idx & 15;
            cp16s(vd + (unsigned)(vrow * 272 + vch * 16), Vg0 + (size_t)vrow * MM + vch * 8);
        }
        if (tid < 16) cp16s(smem_u32(Mb) + tid * 16, Mg0 + tid * 8);
        asm volatile("cp.async.commit_group;");
    }

    // ---- Q fragments (g_q is pre-scaled by 0.125*log2e) ----
    int r0g[2];
    unsigned qf[2][4][4];
    #pragma unroll
    for (int m = 0; m < 2; ++m) {
        r0g[m] = b * SS + qb + w * 32 + m * 16 + lq;
        const unsigned* Qw  = (const unsigned*)(Q + (size_t)r0g[m] * DD + h * DKK);
        const unsigned* Qw8 = (const unsigned*)(Q + (size_t)(r0g[m] + 8) * DD + h * DKK);
        #pragma unroll
        for (int ks = 0; ks < 4; ++ks) {
            qf[m][ks][0] = Qw [8 * ks + lr];
            qf[m][ks][1] = Qw8[8 * ks + lr];
            qf[m][ks][2] = Qw [8 * ks + 4 + lr];
            qf[m][ks][3] = Qw8[8 * ks + 4 + lr];
        }
    }

    float oacc[2][8][4];
    #pragma unroll
    for (int m = 0; m < 2; ++m)
        #pragma unroll
        for (int nt = 0; nt < 8; ++nt)
            #pragma unroll
            for (int i = 0; i < 4; ++i) oacc[m][nt][i] = 0.f;
    float lacc[2][4];   // row-sum accumulators via ones-MMA (c0=row lq, c2=row lq+8)
    #pragma unroll
    for (int m = 0; m < 2; ++m)
        #pragma unroll
        for (int i = 0; i < 4; ++i) lacc[m][i] = 0.f;

    for (int t = 0; t < NT2; ++t) {
        asm volatile("cp.async.wait_group 0;");
        __syncthreads();
        if (t + 1 < NT2) {
            const int s = (t + 1) & 1;
            unsigned kd = smem_u32(Kb + s * KBUFW);
            unsigned vd = smem_u32(Vb + s * VBUFW);
            const __half* Kg = Kg0 + (size_t)((t + 1) * 128) * DD;
            const __half* Vg = Vg0 + (t + 1) * 128;
            #pragma unroll
            for (int l = 0; l < 8; ++l) {
                int idx = tid + l * 128;
                int krow = idx >> 3, kch = idx & 7;
                cp16s(kd + (unsigned)(krow * 144 + kch * 16), Kg + (size_t)krow * DD + kch * 8);
                int vrow = idx >> 4, vch = idx & 15;
                cp16s(vd + (unsigned)(vrow * 272 + vch * 16), Vg + (size_t)vrow * MM + vch * 8);
            }
            if (tid < 16) cp16s(smem_u32(Mb + s * 64) + tid * 16, Mg0 + (t + 1) * 128 + tid * 8);
            asm volatile("cp.async.commit_group;");
        }

        const unsigned ksb = smem_u32(Kb + (t & 1) * KBUFW);
        const unsigned vsb = smem_u32(Vb + (t & 1) * VBUFW);
        const unsigned* Mw = Mb + (t & 1) * 64;

        #pragma unroll
        for (int hk = 0; hk < 4; ++hk) {   // four 32-key quarters
            // ---- S = Q K^T for keys [32hk, 32hk+32) ----
            float sacc[2][4][4];
            #pragma unroll
            for (int m = 0; m < 2; ++m)
                #pragma unroll
                for (int nt = 0; nt < 4; ++nt)
                    #pragma unroll
                    for (int i = 0; i < 4; ++i) sacc[m][nt][i] = 0.f;
            #pragma unroll
            for (int ks = 0; ks < 4; ++ks) {
                #pragma unroll
                for (int n2 = 0; n2 < 2; ++n2) {
                    unsigned b00, b01, b10, b11;
                    unsigned ad = ksb + (unsigned)(((hk * 32 + n2 * 16) * FKW + ks * 8) * 4) + lmBk;
                    ldsm4(b00, b01, b10, b11, ad);
                    mma16(sacc[0][2 * n2],     qf[0][ks][0], qf[0][ks][1], qf[0][ks][2], qf[0][ks][3], b00, b01);
                    mma16(sacc[1][2 * n2],     qf[1][ks][0], qf[1][ks][1], qf[1][ks][2], qf[1][ks][3], b00, b01);
                    mma16(sacc[0][2 * n2 + 1], qf[0][ks][0], qf[0][ks][1], qf[0][ks][2], qf[0][ks][3], b10, b11);
                    mma16(sacc[1][2 * n2 + 1], qf[1][ks][0], qf[1][ks][1], qf[1][ks][2], qf[1][ks][3], b10, b11);
                }
            }

            // ---- softmax: p = ex2(s) * mask (pure f16x2; no fp32 cvt/adds) ----
            unsigned ps[2][4][2];
            #pragma unroll
            for (int nt = 0; nt < 4; ++nt) {
                unsigned mku = Mw[hk * 16 + nt * 4 + lr];
                __half2 mk2 = *reinterpret_cast<__half2*>(&mku);
                #pragma unroll
                for (int m = 0; m < 2; ++m) {
                    unsigned p01 = ex2h2(pack_h2(sacc[m][nt][0], sacc[m][nt][1]));
                    unsigned p23 = ex2h2(pack_h2(sacc[m][nt][2], sacc[m][nt][3]));
                    __half2 hp01 = __hmul2(*reinterpret_cast<__half2*>(&p01), mk2);
                    __half2 hp23 = __hmul2(*reinterpret_cast<__half2*>(&p23), mk2);
                    ps[m][nt][0] = *reinterpret_cast<unsigned*>(&hp01);
                    ps[m][nt][1] = *reinterpret_cast<unsigned*>(&hp23);
                }
            }

            // ---- O += P V; l += P @ ones (constant B-fragment, no ldsm) ----
            #pragma unroll
            for (int ks2 = 0; ks2 < 2; ++ks2) {
                mma16(lacc[0], ps[0][2 * ks2][0], ps[0][2 * ks2][1],
                               ps[0][2 * ks2 + 1][0], ps[0][2 * ks2 + 1][1], ONES, ONES);
                mma16(lacc[1], ps[1][2 * ks2][0], ps[1][2 * ks2][1],
                               ps[1][2 * ks2 + 1][0], ps[1][2 * ks2 + 1][1], ONES, ONES);
                #pragma unroll
                for (int n2 = 0; n2 < 4; ++n2) {
                    unsigned b00, b01, b10, b11;
                    unsigned ad = vsb + (unsigned)((n2 * 16 * FVW + hk * 16 + ks2 * 8) * 4) + lmBv;
                    ldsm4(b00, b01, b10, b11, ad);
                    mma16(oacc[0][2 * n2],     ps[0][2 * ks2][0], ps[0][2 * ks2][1],
                                               ps[0][2 * ks2 + 1][0], ps[0][2 * ks2 + 1][1], b00, b01);
                    mma16(oacc[1][2 * n2],     ps[1][2 * ks2][0], ps[1][2 * ks2][1],
                                               ps[1][2 * ks2 + 1][0], ps[1][2 * ks2 + 1][1], b00, b01);
                    mma16(oacc[0][2 * n2 + 1], ps[0][2 * ks2][0], ps[0][2 * ks2][1],
                                               ps[0][2 * ks2 + 1][0], ps[0][2 * ks2 + 1][1], b10, b11);
                    mma16(oacc[1][2 * n2 + 1], ps[1][2 * ks2][0], ps[1][2 * ks2][1],
                                               ps[1][2 * ks2 + 1][0], ps[1][2 * ks2 + 1][1], b10, b11);
                }
            }
        }
    }

    // lacc[m][0] = sum_k p for row lq (all columns identical); lacc[m][2] for row lq+8
    #pragma unroll
    for (int m = 0; m < 2; ++m) {
        const float inv0 = 1.f / lacc[m][0], inv1 = 1.f / lacc[m][2];
        __half* X0 = X + (size_t)r0g[m] * DD + h * DKK;
        __half* X8 = X + (size_t)(r0g[m] + 8) * DD + h * DKK;
        #pragma unroll
        for (int nt = 0; nt < 8; ++nt) {
            int c = nt * 8 + 2 * lr;
            *reinterpret_cast<unsigned*>(&X0[c]) = pack_h2(oacc[m][nt][0] * inv0, oacc[m][nt][1] * inv0);
            *reinterpret_cast<unsigned*>(&X8[c]) = pack_h2(oacc[m][nt][2] * inv1, oacc[m][nt][3] * inv1);
        }
    }
}

// ---------------- launch ----------------
extern "C" void kernel_launch(void* const* d_in, const int* in_sizes, int n_in,
                              void* d_out, int out_size)
{
    const float* query = (const float*)d_in[0];
    const float* key   = (const float*)d_in[1];
    const float* value = (const float*)d_in[2];
    const int*   mask  = (const int*)  d_in[3];
    const float* wq = (const float*)d_in[4];
    const float* bq = (const float*)d_in[5];
    const float* wk = (const float*)d_in[6];
    const float* bk = (const float*)d_in[7];
    const float* wv = (const float*)d_in[8];
    const float* bv = (const float*)d_in[9];
    const float* wo = (const float*)d_in[10];
    const float* bo = (const float*)d_in[11];
    float* out = (float*)d_out;

    __half *inh, *wh, *mh, *q, *k, *vt, *x;
    cudaGetSymbolAddress((void**)&inh, g_inh);
    cudaGetSymbolAddress((void**)&wh,  g_wh);
    cudaGetSymbolAddress((void**)&mh,  g_mh);
    cudaGetSymbolAddress((void**)&q,   g_q);
    cudaGetSymbolAddress((void**)&k,   g_k);
    cudaGetSymbolAddress((void**)&vt,  g_vt);
    cudaGetSymbolAddress((void**)&x,   g_x);

    cudaFuncSetAttribute(gemm_h,  cudaFuncAttributeMaxDynamicSharedMemorySize, GEMM_SMEM);
    cudaFuncSetAttribute(flash_h, cudaFuncAttributeMaxDynamicSharedMemorySize, FLASH_SMEM);

    // 0) convert inputs + weights (wq pre-scaled by CSC) + mask to fp16
    dim3 gpr((MM * DD / 4 + 255) / 256, 1, 8);
    tohalf<<<gpr, 256>>>(query, key, value, wq, wk, wv, wo, mask, inh, wh, mh);

    // 1) Q,K projections (fp16 out, col bias; Q bias scaled by CSC to match wq)
    dim3 gqk(DD / 128, MM / 128, 2);
    gemm_h<<<gqk, 256, GEMM_SMEM>>>(inh, inh + (size_t)MM * DD,
                                    wh,  wh  + (size_t)DD * DD,
                                    bq, bk,
                                    q, k,
                                    DD, 0, 0, CSC, 1.0f);

    // 2) V projection TRANSPOSED: Vt[1024x4096] = Wv @ value^T + bv (row bias)
    dim3 gvt(MM / 128, DD / 128, 1);
    gemm_h<<<gvt, 256, GEMM_SMEM>>>(wh + 2ull * DD * DD, wh + 2ull * DD * DD,
                                    inh + 2ull * MM * DD, inh + 2ull * MM * DD,
                                    bv, bv,
                                    vt, vt,
                                    MM, 0, 1, 1.0f, 1.0f);

    // 3) flash attention (128-key tiles, 2-stage, MMA row sums)
    dim3 gfa(SS / 128, HH, BB);
    flash_h<<<gfa, 128, FLASH_SMEM>>>(q, k, vt, mh, x);

    // 4) output projection (fp32 out)
    dim3 go(DD / 128, MM / 128, 1);
    gemm_h<<<go, 256, GEMM_SMEM>>>(x, x,
                                   wh + 3ull * DD * DD, wh + 3ull * DD * DD,
                                   bo, bo,
                                   out, out,
                                   DD, 1, 0, 1.0f, 1.0f);
}